// round 13
// baseline (speedup 1.0000x reference)
#include <cuda_runtime.h>

// SoftRank via linear bucket-histogram rank + narrow tanh window.
// out[b,j,c] = (1/N) * sum_i sigmoid(1000*(x[b,j,c]-x[b,i,c]))
//
// Per (b,c) column (one CTA, 1024 threads):
//   1. histogram 1024 values into 4096 linear buckets over [-5,5] (smem atomics)
//   2. block exclusive prefix sum, 4 buckets/thread (uint4), all warps
//      redundantly scan warp totals, sentinel cnt[NBKT]=N
//   3. scatter values into bucket order
//   4. own-element epilogue over fixed bucket range [bk-2, bk+2] (provable
//      superset of the +/-W window since W*INV_W = 1.024 < 2; tanh.approx
//      saturation makes out-of-window scanned elements contribute their exact
//      saturated 0/1 value, so a superset scan is always correct).
//      rank = prefix of buckets < bk-2 (each contributes 1; aggregate tail err
//      410*e^-2.5/1000/N ~ 3.3e-5, model validated over rounds 8-11).

#define NN       1024
#define CC       16
#define BB       8
#define NBKT     4096
#define RANGE_LO (-5.0f)
#define INV_W    409.6f          // NBKT / 10.0
#define WINDOW   0.0025f         // cutoff arg >= 2.5; WINDOW*INV_W = 1.024

__device__ __forceinline__ float fast_tanh(float x) {
    float r;
    asm("tanh.approx.f32 %0, %1;" : "=f"(r) : "f"(x));
    return r;
}

__global__ __launch_bounds__(NN) void softrank_bucket7_kernel(
    const float* __restrict__ x, float* __restrict__ out)
{
    const int b = blockIdx.x >> 4;       // / CC
    const int c = blockIdx.x & (CC - 1); // % CC

    __shared__ unsigned cnt[NBKT + 4];   // counts -> exclusive prefix; [NBKT]=N sentinel
    __shared__ float    skey[NN];        // values in bucket order
    __shared__ unsigned wsum[32];

    const int t    = threadIdx.x;
    const int lane = t & 31;
    const int wid  = t >> 5;

    const float v = x[(b * NN + t) * CC + c];   // long-latency, issued first
    ((uint4*)cnt)[t] = make_uint4(0u, 0u, 0u, 0u);
    int bk = (int)((v - RANGE_LO) * INV_W);
    bk = min(max(bk, 0), NBKT - 1);
    __syncthreads();

    // ---- histogram; slot = within-bucket ordinal ----
    const unsigned slot = atomicAdd(&cnt[bk], 1u);
    __syncthreads();

    // ---- block exclusive prefix sum over 4096 counts, 4 per thread ----
    const uint4 c4 = ((uint4*)cnt)[t];
    const unsigned tsum = c4.x + c4.y + c4.z + c4.w;

    unsigned inc = tsum;                 // warp-inclusive scan of thread sums
    #pragma unroll
    for (int j = 1; j < 32; j <<= 1) {
        unsigned n = __shfl_up_sync(0xffffffffu, inc, j);
        if (lane >= j) inc += n;
    }
    if (lane == 31) wsum[wid] = inc;
    __syncthreads();

    // every warp redundantly scans the 32 warp totals (no wid-0 wait)
    unsigned wv = wsum[lane];
    unsigned wi = wv;
    #pragma unroll
    for (int j = 1; j < 32; j <<= 1) {
        unsigned n = __shfl_up_sync(0xffffffffu, wi, j);
        if (lane >= j) wi += n;
    }
    const unsigned wexcl = __shfl_sync(0xffffffffu, wi - wv, wid);

    const unsigned texcl = wexcl + (inc - tsum);
    uint4 p4;
    p4.x = texcl;
    p4.y = texcl + c4.x;
    p4.z = texcl + c4.x + c4.y;
    p4.w = texcl + c4.x + c4.y + c4.z;
    ((uint4*)cnt)[t] = p4;
    if (t == 0) cnt[NBKT] = (unsigned)NN;   // branchless end lookup
    __syncthreads();

    // ---- scatter into bucket order ----
    skey[cnt[bk] + slot] = v;
    __syncthreads();

    // ---- own-element epilogue over fixed superset range [bk-2, bk+2] ----
    const int b_lo = max(bk - 2, 0);
    const int b_hi = min(bk + 2, NBKT - 1);

    const unsigned start = cnt[b_lo];
    const unsigned end   = cnt[b_hi + 1];

    const float a = 500.0f * v;
    float s0 = 0.0f, s1 = 0.0f;
    unsigned i = start;
    for (; i + 1 < end; i += 2) {        // 2-way ILP on LDS + MUFU
        s0 += fast_tanh(fmaf(-500.0f, skey[i],     a));
        s1 += fast_tanh(fmaf(-500.0f, skey[i + 1], a));
    }
    if (i < end)
        s0 += fast_tanh(fmaf(-500.0f, skey[i], a));

    const float sum = (float)start
                    + 0.5f * (float)(end - start)
                    + 0.5f * (s0 + s1);

    out[(b * NN + t) * CC + c] = sum * (1.0f / (float)NN);
}

extern "C" void kernel_launch(void* const* d_in, const int* in_sizes, int n_in,
                              void* d_out, int out_size)
{
    const float* x = (const float*)d_in[0];
    float* out = (float*)d_out;
    softrank_bucket7_kernel<<<BB * CC, NN>>>(x, out);
}